// round 8
// baseline (speedup 1.0000x reference)
#include <cuda_runtime.h>
#include <math.h>

#define Bn 4
#define Dn 64
#define Hn 64
#define Wn 64
#define CHn 150
#define PLANE 4096
#define VOL   262144
#define VOX   1048576
#define NBLK  512

typedef unsigned long long ull;

__device__ float g_p[VOX];
__device__ float g_c[VOX];      // r * (1 - p)
__device__ float g_v[VOX];      // ping-pong buffer
__device__ unsigned g_flag[NBLK];  // per-block iteration flags (monotonic)

// ---------------- packed f32x2 helpers (sm_103a) ----------------
__device__ __forceinline__ ull pk2(float a, float b) {
    ull r; asm("mov.b64 %0, {%1, %2};" : "=l"(r) : "f"(a), "f"(b)); return r;
}
__device__ __forceinline__ void upk2(ull v, float& a, float& b) {
    asm("mov.b64 {%0, %1}, %2;" : "=f"(a), "=f"(b) : "l"(v));
}
__device__ __forceinline__ ull fma2(ull a, ull b, ull c) {
    ull d; asm("fma.rn.f32x2 %0, %1, %2, %3;" : "=l"(d) : "l"(a), "l"(b), "l"(c));
    return d;
}
__device__ __forceinline__ float4 max4(float4 a, float4 b) {
    return make_float4(fmaxf(a.x, b.x), fmaxf(a.y, b.y),
                       fmaxf(a.z, b.z), fmaxf(a.w, b.w));
}
__device__ __forceinline__ float4 ldcg4(const float4* p) {
    float4 v;
    asm volatile("ld.global.cg.v4.f32 {%0,%1,%2,%3}, [%4];"
                 : "=f"(v.x), "=f"(v.y), "=f"(v.z), "=f"(v.w) : "l"(p));
    return v;
}
__device__ __forceinline__ unsigned ld_acquire(unsigned* p) {
    unsigned v;
    asm volatile("ld.acquire.gpu.global.u32 %0, [%1];"
                 : "=r"(v) : "l"(p) : "memory");
    return v;
}
__device__ __forceinline__ void st_release(unsigned* p, unsigned v) {
    asm volatile("st.release.gpu.global.u32 [%0], %1;" :: "l"(p), "r"(v) : "memory");
}

// ---------------------------------------------------------------------------
// Kernel 1: p = sigmoid(sum_c pw[c]*relu(conv3x3x3_c(x)+b[c]))
//           writes g_p, g_c = r*(1-p), v0 = r into vout.  (unchanged)
// ---------------------------------------------------------------------------
#define DCH 4
#define HT  16
#define XROW 68
#define XHL 18
#define XDL 6
#define NPAIR 75

__global__ __launch_bounds__(256) void compute_p_kernel(
    const float* __restrict__ image, const float* __restrict__ hw,
    const float* __restrict__ hb,    const float* __restrict__ pw,
    float* __restrict__ vout)
{
    __shared__ float  xs[XDL * XHL * XROW];
    __shared__ float4 ws4[NPAIR * 28];
    __shared__ float4 bp4[NPAIR];
    __shared__ float4 pp4[NPAIR];

    const int tid = threadIdx.x;

    for (int i = tid; i < NPAIR * 27; i += 256) {
        const int pr = i / 27, t = i % 27;
        const float wA = hw[(pr * 2) * 27 + t];
        const float wB = hw[(pr * 2 + 1) * 27 + t];
        ws4[pr * 28 + t] = make_float4(wA, wA, wB, wB);
    }
    for (int i = tid; i < NPAIR; i += 256) {
        const float bA = hb[i * 2], bB = hb[i * 2 + 1];
        const float pA = pw[i * 2], pB = pw[i * 2 + 1];
        bp4[i] = make_float4(bA, bA, bB, bB);
        pp4[i] = make_float4(pA, pA, pB, pB);
    }

    const int d0 = blockIdx.x * DCH;
    const int h0 = blockIdx.y * HT;
    const int b  = blockIdx.z;
    const float* xg = image + (size_t)b * 2 * VOL;
    const float* rg = xg + VOL;

    for (int i = tid; i < XDL * XHL * 66; i += 256) {
        int wl = i % 66; int rest = i / 66;
        int hl = rest % XHL; int dl = rest / XHL;
        int gw = wl - 1, gh = h0 + hl - 1, gd = d0 + dl - 1;
        float v = 0.0f;
        if (gw >= 0 && gw < Wn && gh >= 0 && gh < Hn && gd >= 0 && gd < Dn)
            v = xg[((size_t)gd * Hn + gh) * Wn + gw];
        xs[(dl * XHL + hl) * XROW + wl] = v;
    }
    __syncthreads();

    const int wt = tid & 15;
    const int ht = tid >> 4;
    const int w0 = wt * 4;

    for (int dl = 0; dl < DCH; dl++) {
        ull P[9][5];
        #pragma unroll
        for (int r9 = 0; r9 < 9; r9++) {
            const int dz = r9 / 3, hy = r9 % 3;
            const float* base = &xs[((dl + dz) * XHL + (ht + hy)) * XROW + w0];
            float4 a  = *(const float4*)base;
            float2 b2 = *(const float2*)(base + 4);
            P[r9][0] = pk2(a.x, a.y);
            P[r9][1] = pk2(a.y, a.z);
            P[r9][2] = pk2(a.z, a.w);
            P[r9][3] = pk2(a.w, b2.x);
            P[r9][4] = pk2(b2.x, b2.y);
        }

        ull z01 = 0ull, z23 = 0ull;

        #pragma unroll 1
        for (int cp = 0; cp < NPAIR; cp++) {
            const ulonglong2* wp = (const ulonglong2*)(ws4 + cp * 28);
            const ulonglong2 bb = ((const ulonglong2*)bp4)[cp];
            ull aA01 = bb.x, aA23 = bb.x;
            ull aB01 = bb.y, aB23 = bb.y;
            #pragma unroll
            for (int t = 0; t < 27; t++) {
                const ulonglong2 w2 = wp[t];
                const int r9 = t / 3, kx = t % 3;
                aA01 = fma2(w2.x, P[r9][kx],     aA01);
                aA23 = fma2(w2.x, P[r9][kx + 2], aA23);
                aB01 = fma2(w2.y, P[r9][kx],     aB01);
                aB23 = fma2(w2.y, P[r9][kx + 2], aB23);
            }
            float a0, a1, a2, a3, b0, b1, b2, b3;
            upk2(aA01, a0, a1); upk2(aA23, a2, a3);
            upk2(aB01, b0, b1); upk2(aB23, b2, b3);
            a0 = fmaxf(a0, 0.f); a1 = fmaxf(a1, 0.f);
            a2 = fmaxf(a2, 0.f); a3 = fmaxf(a3, 0.f);
            b0 = fmaxf(b0, 0.f); b1 = fmaxf(b1, 0.f);
            b2 = fmaxf(b2, 0.f); b3 = fmaxf(b3, 0.f);
            const ulonglong2 pv = ((const ulonglong2*)pp4)[cp];
            z01 = fma2(pv.x, pk2(a0, a1), z01);
            z23 = fma2(pv.x, pk2(a2, a3), z23);
            z01 = fma2(pv.y, pk2(b0, b1), z01);
            z23 = fma2(pv.y, pk2(b2, b3), z23);
        }

        float z0, z1, z2, z3;
        upk2(z01, z0, z1); upk2(z23, z2, z3);

        const int gd = d0 + dl, gh = h0 + ht;
        const size_t o = ((size_t)b * Dn + gd) * PLANE + gh * Wn + w0;
        const float4 r4 = *(const float4*)&rg[((size_t)gd * Hn + gh) * Wn + w0];

        const float p0 = 1.f / (1.f + __expf(-z0));
        const float p1 = 1.f / (1.f + __expf(-z1));
        const float p2 = 1.f / (1.f + __expf(-z2));
        const float p3 = 1.f / (1.f + __expf(-z3));

        *(float4*)&g_p[o]  = make_float4(p0, p1, p2, p3);
        *(float4*)&g_c[o]  = make_float4(r4.x * (1.f - p0), r4.y * (1.f - p1),
                                         r4.z * (1.f - p2), r4.w * (1.f - p3));
        *(float4*)&vout[o] = r4;
    }
}

// ---------------------------------------------------------------------------
// Kernel 2: PERSISTENT propagation, NO global barrier.
// Each block publishes a per-block flag after each iteration (st.release)
// and waits only on its <=5 neighbor blocks (ld.acquire + nanosleep),
// one neighbor per thread in parallel.  Flags are monotonic -> replay-safe.
// flag_nb >= base+J covers both "neighbor's J-1 output is readable" and
// "neighbor finished reading the buffer I'm about to overwrite".
// ---------------------------------------------------------------------------
__global__ __launch_bounds__(256, 4) void prop_kernel(
    float4* __restrict__ bufA, float4* __restrict__ bufB,
    const int* __restrict__ kptr)
{
    __shared__ float4 vz[34 * 16];
    __shared__ float4 p_s[32 * 16];
    __shared__ float4 c_s[32 * 16];
    __shared__ unsigned s_base;

    const int blk = blockIdx.x;
    const int bd  = blk >> 1;
    const int hs  = blk & 1;
    const int h0  = hs * 32;
    const int d   = bd & 63;
    const int tid = threadIdx.x;
    const int ks  = *kptr;

    const size_t base = (size_t)bd * 1024;
    const long long dm = (d > 0)  ? -1024 : 0;
    const long long dp = (d < 63) ?  1024 : 0;

    // flag base: own flag, quiescent at kernel entry (all flags equal)
    if (tid == 0) s_base = ld_acquire(&g_flag[blk]);

    // my neighbor (thread tid waits on neighbor tid, tid<5)
    int nbid = -1;
    if (tid == 0) nbid = bd * 2 + (1 - hs);                    // partner half
    else if (tid == 1 && d > 0)  nbid = (bd - 1) * 2 + hs;
    else if (tid == 2 && d < 63) nbid = (bd + 1) * 2 + hs;
    else if (tid == 3 && d > 0)  nbid = (bd - 1) * 2 + (1 - hs);
    else if (tid == 4 && d < 63) nbid = (bd + 1) * 2 + (1 - hs);

    float4 cen[2];
    #pragma unroll
    for (int q = 0; q < 2; q++) {
        const int i  = tid + q * 256;
        const int ro = i >> 4, c4 = i & 15;
        const size_t off = base + (h0 + ro) * 16 + c4;
        p_s[i] = ((const float4*)g_p)[off];
        c_s[i] = ((const float4*)g_c)[off];
        cen[q] = ldcg4(bufA + off);
    }
    __syncthreads();
    const unsigned fbase = s_base;

    float4* src = bufA;
    float4* dst = bufB;

    for (int it = 0; it < 30; it++) {
        // ---- wait for neighbors to reach iteration 'it' ----
        if (it > 0) {
            if (nbid >= 0) {
                const unsigned target = fbase + (unsigned)it;
                while ((int)(ld_acquire(&g_flag[nbid]) - target) < 0)
                    __nanosleep(32);
            }
            __syncthreads();   // acquire by tid<5 -> visible to whole block
        }

        // ---- stage 1: d-max into SMEM ----
        #pragma unroll
        for (int q = 0; q < 2; q++) {
            const int i  = tid + q * 256;
            const int ro = i >> 4, c4 = i & 15;
            const size_t off = base + (h0 + ro) * 16 + c4;
            float4 m = max4(cen[q], ldcg4(src + off + dm));
            m = max4(m, ldcg4(src + off + dp));
            vz[(ro + 1) * 16 + c4] = m;
        }
        if (tid < 32) {                          // h-halo rows
            const int c4 = tid & 15;
            const int hr = (tid < 16) ? -1 : 32;
            const int gh = min(63, max(0, h0 + hr));
            const size_t off = base + gh * 16 + c4;
            float4 m = ldcg4(src + off);
            m = max4(m, ldcg4(src + off + dm));
            m = max4(m, ldcg4(src + off + dp));
            vz[(hr + 1) * 16 + c4] = m;
        }
        __syncthreads();

        // ---- stage 2: h-max + w-max + update ----
        #pragma unroll
        for (int q = 0; q < 2; q++) {
            const int i  = tid + q * 256;
            const int ro = i >> 4, c4 = i & 15;

            float4 hm = max4(max4(vz[ro * 16 + c4], vz[(ro + 1) * 16 + c4]),
                             vz[(ro + 2) * 16 + c4]);

            float lf = __shfl_up_sync(0xffffffffu, hm.w, 1);
            float rt = __shfl_down_sync(0xffffffffu, hm.x, 1);
            if (c4 == 0)  lf = hm.x;
            if (c4 == 15) rt = hm.w;

            float4 m;
            m.x = fmaxf(lf,   fmaxf(hm.x, hm.y));
            m.y = fmaxf(hm.x, fmaxf(hm.y, hm.z));
            m.z = fmaxf(hm.y, fmaxf(hm.z, hm.w));
            m.w = fmaxf(hm.z, fmaxf(hm.w, rt));

            const float4 pp = p_s[i];
            const float4 cc = c_s[i];
            float4 nv;
            nv.x = fmaxf(cen[q].x, fmaf(pp.x, m.x, cc.x));
            nv.y = fmaxf(cen[q].y, fmaf(pp.y, m.y, cc.y));
            nv.z = fmaxf(cen[q].z, fmaf(pp.z, m.z, cc.z));
            nv.w = fmaxf(cen[q].w, fmaf(pp.w, m.w, cc.w));
            if (it >= ks) nv = cen[q];

            dst[base + (h0 + ro) * 16 + c4] = nv;
            cen[q] = nv;
        }

        // ---- publish: all my stores -> flag release ----
        __syncthreads();
        if (tid == 0) st_release(&g_flag[blk], fbase + (unsigned)it + 1u);

        float4* t = dst; dst = src; src = t;
    }
}

// ---------------------------------------------------------------------------
extern "C" void kernel_launch(void* const* d_in, const int* in_sizes, int n_in,
                              void* d_out, int out_size)
{
    const float* image = (const float*)d_in[0];
    const float* hw    = (const float*)d_in[1];
    const float* hb    = (const float*)d_in[2];
    const float* pw    = (const float*)d_in[3];
    const int*   kptr  = (const int*)d_in[4];
    float* out = (float*)d_out;

    void* pv = nullptr;
    cudaGetSymbolAddress(&pv, g_v);
    float* vbuf = (float*)pv;

    // v0 -> out (src of iter 0); 30 iterations end with final write in d_out.
    compute_p_kernel<<<dim3(16, 4, 4), 256>>>(image, hw, hb, pw, out);
    prop_kernel<<<NBLK, 256>>>((float4*)out, (float4*)vbuf, kptr);
}

// round 9
// speedup vs baseline: 1.5826x; 1.5826x over previous
#include <cuda_runtime.h>
#include <math.h>

#define Bn 4
#define Dn 64
#define Hn 64
#define Wn 64
#define CHn 150
#define PLANE 4096
#define VOL   262144
#define VOX   1048576

typedef unsigned long long ull;

__device__ float g_p[VOX];
__device__ float g_c[VOX];   // r * (1 - p)
__device__ float g_v[VOX];   // ping-pong buffer

// ---------------- packed f32x2 helpers (sm_103a) ----------------
__device__ __forceinline__ ull pk2(float a, float b) {
    ull r; asm("mov.b64 %0, {%1, %2};" : "=l"(r) : "f"(a), "f"(b)); return r;
}
__device__ __forceinline__ void upk2(ull v, float& a, float& b) {
    asm("mov.b64 {%0, %1}, %2;" : "=f"(a), "=f"(b) : "l"(v));
}
__device__ __forceinline__ ull fma2(ull a, ull b, ull c) {
    ull d; asm("fma.rn.f32x2 %0, %1, %2, %3;" : "=l"(d) : "l"(a), "l"(b), "l"(c));
    return d;
}
__device__ __forceinline__ float4 max4(float4 a, float4 b) {
    return make_float4(fmaxf(a.x, b.x), fmaxf(a.y, b.y),
                       fmaxf(a.z, b.z), fmaxf(a.w, b.w));
}

// ---------------------------------------------------------------------------
// Kernel 1: p = sigmoid(sum_c pw[c]*relu(conv3x3x3_c(x)+b[c]))
//           writes g_p, g_c = r*(1-p), v0 = r into vout.
// At the fma2 roofline (~119 us): 63.5M warp-instr / (148 SM * 2 instr/cyc).
// ---------------------------------------------------------------------------
#define DCH 4
#define HT  16
#define XROW 68
#define XHL 18
#define XDL 6
#define NPAIR 75

__global__ __launch_bounds__(256) void compute_p_kernel(
    const float* __restrict__ image, const float* __restrict__ hw,
    const float* __restrict__ hb,    const float* __restrict__ pw,
    float* __restrict__ vout)
{
    __shared__ float  xs[XDL * XHL * XROW];
    __shared__ float4 ws4[NPAIR * 28];
    __shared__ float4 bp4[NPAIR];
    __shared__ float4 pp4[NPAIR];

    const int tid = threadIdx.x;

    for (int i = tid; i < NPAIR * 27; i += 256) {
        const int pr = i / 27, t = i % 27;
        const float wA = hw[(pr * 2) * 27 + t];
        const float wB = hw[(pr * 2 + 1) * 27 + t];
        ws4[pr * 28 + t] = make_float4(wA, wA, wB, wB);
    }
    for (int i = tid; i < NPAIR; i += 256) {
        const float bA = hb[i * 2], bB = hb[i * 2 + 1];
        const float pA = pw[i * 2], pB = pw[i * 2 + 1];
        bp4[i] = make_float4(bA, bA, bB, bB);
        pp4[i] = make_float4(pA, pA, pB, pB);
    }

    const int d0 = blockIdx.x * DCH;
    const int h0 = blockIdx.y * HT;
    const int b  = blockIdx.z;
    const float* xg = image + (size_t)b * 2 * VOL;
    const float* rg = xg + VOL;

    for (int i = tid; i < XDL * XHL * 66; i += 256) {
        int wl = i % 66; int rest = i / 66;
        int hl = rest % XHL; int dl = rest / XHL;
        int gw = wl - 1, gh = h0 + hl - 1, gd = d0 + dl - 1;
        float v = 0.0f;
        if (gw >= 0 && gw < Wn && gh >= 0 && gh < Hn && gd >= 0 && gd < Dn)
            v = xg[((size_t)gd * Hn + gh) * Wn + gw];
        xs[(dl * XHL + hl) * XROW + wl] = v;
    }
    __syncthreads();

    const int wt = tid & 15;
    const int ht = tid >> 4;
    const int w0 = wt * 4;

    for (int dl = 0; dl < DCH; dl++) {
        ull P[9][5];
        #pragma unroll
        for (int r9 = 0; r9 < 9; r9++) {
            const int dz = r9 / 3, hy = r9 % 3;
            const float* base = &xs[((dl + dz) * XHL + (ht + hy)) * XROW + w0];
            float4 a  = *(const float4*)base;
            float2 b2 = *(const float2*)(base + 4);
            P[r9][0] = pk2(a.x, a.y);
            P[r9][1] = pk2(a.y, a.z);
            P[r9][2] = pk2(a.z, a.w);
            P[r9][3] = pk2(a.w, b2.x);
            P[r9][4] = pk2(b2.x, b2.y);
        }

        ull z01 = 0ull, z23 = 0ull;

        #pragma unroll 1
        for (int cp = 0; cp < NPAIR; cp++) {
            const ulonglong2* wp = (const ulonglong2*)(ws4 + cp * 28);
            const ulonglong2 bb = ((const ulonglong2*)bp4)[cp];
            ull aA01 = bb.x, aA23 = bb.x;
            ull aB01 = bb.y, aB23 = bb.y;
            #pragma unroll
            for (int t = 0; t < 27; t++) {
                const ulonglong2 w2 = wp[t];
                const int r9 = t / 3, kx = t % 3;
                aA01 = fma2(w2.x, P[r9][kx],     aA01);
                aA23 = fma2(w2.x, P[r9][kx + 2], aA23);
                aB01 = fma2(w2.y, P[r9][kx],     aB01);
                aB23 = fma2(w2.y, P[r9][kx + 2], aB23);
            }
            float a0, a1, a2, a3, b0, b1, b2, b3;
            upk2(aA01, a0, a1); upk2(aA23, a2, a3);
            upk2(aB01, b0, b1); upk2(aB23, b2, b3);
            a0 = fmaxf(a0, 0.f); a1 = fmaxf(a1, 0.f);
            a2 = fmaxf(a2, 0.f); a3 = fmaxf(a3, 0.f);
            b0 = fmaxf(b0, 0.f); b1 = fmaxf(b1, 0.f);
            b2 = fmaxf(b2, 0.f); b3 = fmaxf(b3, 0.f);
            const ulonglong2 pv = ((const ulonglong2*)pp4)[cp];
            z01 = fma2(pv.x, pk2(a0, a1), z01);
            z23 = fma2(pv.x, pk2(a2, a3), z23);
            z01 = fma2(pv.y, pk2(b0, b1), z01);
            z23 = fma2(pv.y, pk2(b2, b3), z23);
        }

        float z0, z1, z2, z3;
        upk2(z01, z0, z1); upk2(z23, z2, z3);

        const int gd = d0 + dl, gh = h0 + ht;
        const size_t o = ((size_t)b * Dn + gd) * PLANE + gh * Wn + w0;
        const float4 r4 = *(const float4*)&rg[((size_t)gd * Hn + gh) * Wn + w0];

        const float p0 = 1.f / (1.f + __expf(-z0));
        const float p1 = 1.f / (1.f + __expf(-z1));
        const float p2 = 1.f / (1.f + __expf(-z2));
        const float p3 = 1.f / (1.f + __expf(-z3));

        *(float4*)&g_p[o]  = make_float4(p0, p1, p2, p3);
        *(float4*)&g_c[o]  = make_float4(r4.x * (1.f - p0), r4.y * (1.f - p1),
                                         r4.z * (1.f - p2), r4.w * (1.f - p3));
        *(float4*)&vout[o] = r4;
    }
}

// ---------------------------------------------------------------------------
// Kernel 2: one propagation iteration.  Block = 32-row half-plane of (b,d).
// ALL independent global loads issued up front (center/d+-1 x2, halo x3,
// p/c x4 -> MLP ~13/thread); p/c latency overlaps stage 1 + barrier.
// ---------------------------------------------------------------------------
__global__ __launch_bounds__(256) void iter_kernel(
    const float4* __restrict__ vin, float4* __restrict__ vout,
    const int* __restrict__ kptr, int it)
{
    __shared__ float4 vz[34 * 16];    // d-max, rows h0-1 .. h0+32 (clamped)

    const int blk = blockIdx.x;
    const int bd  = blk >> 1;         // b*64 + d
    const int h0  = (blk & 1) * 32;
    const int d   = bd & 63;
    const int tid = threadIdx.x;
    const bool skip = (it >= *kptr);

    const size_t base = (size_t)bd * 1024;
    const long long dm = (d > 0)  ? -1024 : 0;
    const long long dp = (d < 63) ?  1024 : 0;

    const int ro0 = tid >> 4;         // 0..15  (q=0 row)
    const int c4  = tid & 15;
    const size_t off0 = base + (h0 + ro0) * 16 + c4;
    const size_t off1 = off0 + 16 * 16;                 // q=1 row (+16 rows)

    // ---- issue ALL independent loads up front ----
    float4 cen0 = vin[off0],      cen1 = vin[off1];
    float4 vm0  = vin[off0 + dm], vm1  = vin[off1 + dm];
    float4 vp0  = vin[off0 + dp], vp1  = vin[off1 + dp];
    const float4 pp0 = ((const float4*)g_p)[off0];
    const float4 pp1 = ((const float4*)g_p)[off1];
    const float4 cc0 = ((const float4*)g_c)[off0];
    const float4 cc1 = ((const float4*)g_c)[off1];

    float4 hcen, hdm, hdp;
    int hrow = 0;
    if (tid < 32) {                   // halo rows h0-1 and h0+32
        const int hc4 = tid & 15;
        const int hr  = (tid < 16) ? -1 : 32;
        const int gh  = min(63, max(0, h0 + hr));
        const size_t hoff = base + gh * 16 + hc4;
        hcen = vin[hoff];
        hdm  = vin[hoff + dm];
        hdp  = vin[hoff + dp];
        hrow = (hr + 1) * 16 + hc4;   // 0..15 or 33*16+..
    }

    // ---- stage 1: d-max into SMEM ----
    vz[(ro0 + 1) * 16 + c4]      = max4(max4(cen0, vm0), vp0);
    vz[(ro0 + 1 + 16) * 16 + c4] = max4(max4(cen1, vm1), vp1);
    if (tid < 32)
        vz[hrow] = max4(max4(hcen, hdm), hdp);
    __syncthreads();

    // ---- stage 2: h-max + w-max + update ----
    #pragma unroll
    for (int q = 0; q < 2; q++) {
        const int ro = ro0 + q * 16;

        float4 hm = max4(max4(vz[ro * 16 + c4], vz[(ro + 1) * 16 + c4]),
                         vz[(ro + 2) * 16 + c4]);

        float lf = __shfl_up_sync(0xffffffffu, hm.w, 1);
        float rt = __shfl_down_sync(0xffffffffu, hm.x, 1);
        if (c4 == 0)  lf = hm.x;      // w==0 edge (also fixes row crossing)
        if (c4 == 15) rt = hm.w;      // w==63 edge

        float4 m;
        m.x = fmaxf(lf,   fmaxf(hm.x, hm.y));
        m.y = fmaxf(hm.x, fmaxf(hm.y, hm.z));
        m.z = fmaxf(hm.y, fmaxf(hm.z, hm.w));
        m.w = fmaxf(hm.z, fmaxf(hm.w, rt));

        const float4 cen = q ? cen1 : cen0;
        const float4 pp  = q ? pp1  : pp0;
        const float4 cc  = q ? cc1  : cc0;

        float4 nv;
        nv.x = fmaxf(cen.x, fmaf(pp.x, m.x, cc.x));
        nv.y = fmaxf(cen.y, fmaf(pp.y, m.y, cc.y));
        nv.z = fmaxf(cen.z, fmaf(pp.z, m.z, cc.z));
        nv.w = fmaxf(cen.w, fmaf(pp.w, m.w, cc.w));

        vout[q ? off1 : off0] = skip ? cen : nv;
    }
}

// ---------------------------------------------------------------------------
extern "C" void kernel_launch(void* const* d_in, const int* in_sizes, int n_in,
                              void* d_out, int out_size)
{
    const float* image = (const float*)d_in[0];
    const float* hw    = (const float*)d_in[1];
    const float* hb    = (const float*)d_in[2];
    const float* pw    = (const float*)d_in[3];
    const int*   kptr  = (const int*)d_in[4];
    float* out = (float*)d_out;

    void* pv = nullptr;
    cudaGetSymbolAddress(&pv, g_v);
    float* vbuf = (float*)pv;

    compute_p_kernel<<<dim3(16, 4, 4), 256>>>(image, hw, hb, pw, out);

    const float* src = out;
    float* dst = vbuf;
    for (int i = 0; i < 30; i++) {
        iter_kernel<<<Bn * Dn * 2, 256>>>((const float4*)src, (float4*)dst, kptr, i);
        float* t = dst; dst = (float*)src; src = t;
    }
    // 30 iterations (even count): final write lands in d_out.
}